// round 13
// baseline (speedup 1.0000x reference)
#include <cuda_runtime.h>
#include <cuda_bf16.h>
#include <math.h>
#include <cstdint>

#define B_ 4
#define T_ 4096
#define D_ 1024
#define H_ 8
#define K_ 128
#define C_ 64
#define NCH 64
#define M_ (B_*T_)
#define RS 129
#define SLICES 4
#define SW 32
#define GSTR 40           // bf16 smem stride for GEMM tiles
#define CAB 136           // chunk_prep bf16 tile stride

// ---------------- scratch -------------------------------------------------------
__device__ float g_xwv [B_*T_*D_];
__device__ float g_gate[B_*T_*D_];
__device__ float g_v   [B_*T_*D_];
__device__ float g_o   [B_*T_*D_];
__device__ float g_beta[B_*T_*H_];
__device__ float g_dec [B_*T_*H_];
__device__ float g_dcum[B_*T_*H_];
__device__ __nv_bfloat16 g_attn_h[B_*H_*NCH*C_*C_], g_attn_l[B_*H_*NCH*C_*C_];
__device__ __nv_bfloat16 g_rk_h [M_*D_], g_rk_l [M_*D_];
__device__ __nv_bfloat16 g_wk_h [M_*D_], g_wk_l [M_*D_];
__device__ __nv_bfloat16 g_wkc_h[M_*D_], g_wkc_l[M_*D_];
__device__ __nv_bfloat16 g_xhi[M_*D_], g_xlo[M_*D_];
__device__ __nv_bfloat16 g_ahi[M_*D_], g_alo[M_*D_];
__device__ __nv_bfloat16 g_Wvhi[D_*D_], g_Wvlo[D_*D_];
__device__ __nv_bfloat16 g_Wghi[D_*D_], g_Wglo[D_*D_];
__device__ __nv_bfloat16 g_Wohi[D_*D_], g_Wolo[D_*D_];

// ---------------- streams/events for graph-captured fork -------------------------
static cudaStream_t s_aux1 = nullptr, s_aux2 = nullptr;
static cudaEvent_t ev_root = nullptr, ev_w = nullptr, ev_p = nullptr, ev_g = nullptr;
static bool s_ok = false;
struct _StreamInit {
    _StreamInit() {
        s_ok = (cudaStreamCreateWithFlags(&s_aux1, cudaStreamNonBlocking) == cudaSuccess) &&
               (cudaStreamCreateWithFlags(&s_aux2, cudaStreamNonBlocking) == cudaSuccess) &&
               (cudaEventCreateWithFlags(&ev_root, cudaEventDisableTiming) == cudaSuccess) &&
               (cudaEventCreateWithFlags(&ev_w, cudaEventDisableTiming) == cudaSuccess) &&
               (cudaEventCreateWithFlags(&ev_p, cudaEventDisableTiming) == cudaSuccess) &&
               (cudaEventCreateWithFlags(&ev_g, cudaEventDisableTiming) == cudaSuccess);
    }
};
static _StreamInit _stream_init_obj;

// ================= low-level helpers ===========================================
__device__ __forceinline__ uint32_t smem_u32(const void* p) {
    uint32_t a;
    asm("{ .reg .u64 t; cvta.to.shared.u64 t, %1; cvt.u32.u64 %0, t; }" : "=r"(a) : "l"(p));
    return a;
}
__device__ __forceinline__ void cpasync16(uint32_t saddr, const void* gaddr) {
    asm volatile("cp.async.cg.shared.global [%0], [%1], 16;" :: "r"(saddr), "l"(gaddr));
}
#define CP_COMMIT() asm volatile("cp.async.commit_group;" ::: "memory")
#define CP_WAIT0()  asm volatile("cp.async.wait_group 0;" ::: "memory")

__device__ __forceinline__ void ldsm4(uint32_t* r, uint32_t saddr) {
    asm volatile("ldmatrix.sync.aligned.m8n8.x4.shared.b16 {%0,%1,%2,%3}, [%4];"
        : "=r"(r[0]), "=r"(r[1]), "=r"(r[2]), "=r"(r[3]) : "r"(saddr));
}
__device__ __forceinline__ void ldsm4t(uint32_t* r, uint32_t saddr) {
    asm volatile("ldmatrix.sync.aligned.m8n8.x4.trans.shared.b16 {%0,%1,%2,%3}, [%4];"
        : "=r"(r[0]), "=r"(r[1]), "=r"(r[2]), "=r"(r[3]) : "r"(saddr));
}
__device__ __forceinline__ void mma16816(float* c, const uint32_t* a, uint32_t b0, uint32_t b1) {
    asm volatile(
        "mma.sync.aligned.m16n8k16.row.col.f32.bf16.bf16.f32 "
        "{%0,%1,%2,%3}, {%4,%5,%6,%7}, {%8,%9}, {%0,%1,%2,%3};"
        : "+f"(c[0]), "+f"(c[1]), "+f"(c[2]), "+f"(c[3])
        : "r"(a[0]), "r"(a[1]), "r"(a[2]), "r"(a[3]), "r"(b0), "r"(b1));
}
__device__ __forceinline__ void bfsplit(float v, __nv_bfloat16& h, __nv_bfloat16& l) {
    h = __float2bfloat16(v);
    l = __float2bfloat16(v - __bfloat162float(h));
}

// ================= fused token prep ==============================================
__global__ void __launch_bounds__(256) prep_tokens(const float* __restrict__ x,
                                                   const float* __restrict__ Wb,
                                                   const float* __restrict__ Wa,
                                                   const float* __restrict__ dt_bias,
                                                   const float* __restrict__ A_log) {
    const int row = blockIdx.x;
    const int t = row & (T_ - 1);
    __shared__ float sx[D_], sxp[D_];
    const int tid = threadIdx.x;
    {
        float4 v = reinterpret_cast<const float4*>(x + (size_t)row * D_)[tid];
        reinterpret_cast<float4*>(sx)[tid] = v;
        float4 vp = (t > 0) ? reinterpret_cast<const float4*>(x + (size_t)(row - 1) * D_)[tid]
                            : make_float4(0.f, 0.f, 0.f, 0.f);
        reinterpret_cast<float4*>(sxp)[tid] = vp;
    }
    __syncthreads();

    {
        float4 v = reinterpret_cast<float4*>(sx)[tid];
        long i = (long)row * D_ + tid * 4;
        __nv_bfloat16 h0, h1, h2, h3, l0, l1, l2, l3;
        bfsplit(v.x, h0, l0); bfsplit(v.y, h1, l1);
        bfsplit(v.z, h2, l2); bfsplit(v.w, h3, l3);
        *reinterpret_cast<__nv_bfloat162*>(g_xhi + i)     = __nv_bfloat162(h0, h1);
        *reinterpret_cast<__nv_bfloat162*>(g_xhi + i + 2) = __nv_bfloat162(h2, h3);
        *reinterpret_cast<__nv_bfloat162*>(g_xlo + i)     = __nv_bfloat162(l0, l1);
        *reinterpret_cast<__nv_bfloat162*>(g_xlo + i + 2) = __nv_bfloat162(l2, l3);
    }

    const int w = tid >> 5, lane = tid & 31;
    {
        float4 xv = reinterpret_cast<float4*>(sx)[w * 32 + lane];
        float4 xs = reinterpret_cast<float4*>(sxp)[w * 32 + lane];
        float s1 = xv.x * xv.x + xv.y * xv.y + xv.z * xv.z + xv.w * xv.w;
        float s2 = xs.x * xs.x + xs.y * xs.y + xs.z * xs.z + xs.w * xs.w;
#pragma unroll
        for (int off = 16; off; off >>= 1) {
            s1 += __shfl_xor_sync(0xffffffffu, s1, off);
            s2 += __shfl_xor_sync(0xffffffffu, s2, off);
        }
        float r1 = rsqrtf(s1 + 1e-6f) * 0.08838834764831845f;
        float r2 = rsqrtf(s2 + 1e-6f);
        long gi = (long)row * D_ + w * K_ + lane * 4;
        __nv_bfloat16 h0, h1, h2, h3, l0, l1, l2, l3;
        bfsplit(xv.x * r1, h0, l0); bfsplit(xv.y * r1, h1, l1);
        bfsplit(xv.z * r1, h2, l2); bfsplit(xv.w * r1, h3, l3);
        *reinterpret_cast<__nv_bfloat162*>(g_rk_h + gi)     = __nv_bfloat162(h0, h1);
        *reinterpret_cast<__nv_bfloat162*>(g_rk_h + gi + 2) = __nv_bfloat162(h2, h3);
        *reinterpret_cast<__nv_bfloat162*>(g_rk_l + gi)     = __nv_bfloat162(l0, l1);
        *reinterpret_cast<__nv_bfloat162*>(g_rk_l + gi + 2) = __nv_bfloat162(l2, l3);
        bfsplit(xs.x * r2, h0, l0); bfsplit(xs.y * r2, h1, l1);
        bfsplit(xs.z * r2, h2, l2); bfsplit(xs.w * r2, h3, l3);
        *reinterpret_cast<__nv_bfloat162*>(g_wk_h + gi)     = __nv_bfloat162(h0, h1);
        *reinterpret_cast<__nv_bfloat162*>(g_wk_h + gi + 2) = __nv_bfloat162(h2, h3);
        *reinterpret_cast<__nv_bfloat162*>(g_wk_l + gi)     = __nv_bfloat162(l0, l1);
        *reinterpret_cast<__nv_bfloat162*>(g_wk_l + gi + 2) = __nv_bfloat162(l2, l3);
    }

    {
        const float* wb = Wb + w * D_;
        const float* wa = Wa + w * D_;
        float db = 0.f, da = 0.f;
        for (int k = lane; k < D_; k += 32) {
            float xv = sx[k];
            db = fmaf(xv, wb[k], db);
            da = fmaf(xv, wa[k], da);
        }
#pragma unroll
        for (int off = 16; off; off >>= 1) {
            db += __shfl_down_sync(0xffffffffu, db, off);
            da += __shfl_down_sync(0xffffffffu, da, off);
        }
        if (lane == 0) {
            g_beta[row * H_ + w] = 1.f / (1.f + __expf(-db));
            float z = da + dt_bias[w];
            float sp = (z > 20.f) ? z : log1pf(__expf(z));
            g_dec[row * H_ + w] = -__expf(A_log[w]) * sp;
        }
    }
}

// ================= weight splits =================================================
__device__ __forceinline__ void split4(const float* __restrict__ src,
                                       __nv_bfloat16* __restrict__ hi,
                                       __nv_bfloat16* __restrict__ lo, long i) {
    float4 v = *reinterpret_cast<const float4*>(src + i);
    __nv_bfloat16 h0, h1, h2, h3, l0, l1, l2, l3;
    bfsplit(v.x, h0, l0); bfsplit(v.y, h1, l1);
    bfsplit(v.z, h2, l2); bfsplit(v.w, h3, l3);
    *reinterpret_cast<__nv_bfloat162*>(hi + i)     = __nv_bfloat162(h0, h1);
    *reinterpret_cast<__nv_bfloat162*>(hi + i + 2) = __nv_bfloat162(h2, h3);
    *reinterpret_cast<__nv_bfloat162*>(lo + i)     = __nv_bfloat162(l0, l1);
    *reinterpret_cast<__nv_bfloat162*>(lo + i + 2) = __nv_bfloat162(l2, l3);
}
__global__ void __launch_bounds__(256) split_w_k(const float* __restrict__ Wv,
                                                 const float* __restrict__ Wg,
                                                 const float* __restrict__ Wo) {
    long i = ((long)blockIdx.x * 256 + threadIdx.x) * 4;
    if (i < 1048576)            split4(Wv, g_Wvhi, g_Wvlo, i);
    else if (i < 2097152)       split4(Wg, g_Wghi, g_Wglo, i - 1048576);
    else                        split4(Wo, g_Wohi, g_Wolo, i - 2097152);
}

// ================= HMMA split-bf16 GEMM ==========================================
#define TILE_E (128 * GSTR)
#define STAGE_E (4 * TILE_E)
__device__ __forceinline__ void gemm_hmma_body(
    const __nv_bfloat16* __restrict__ Ahi, const __nv_bfloat16* __restrict__ Alo,
    const __nv_bfloat16* __restrict__ Bhi, const __nv_bfloat16* __restrict__ Blo,
    float* __restrict__ Cm) {
    extern __shared__ __nv_bfloat16 dsm[];
    const int tid = threadIdx.x;
    const int wid = tid >> 5, lane = tid & 31;
    const int wm = wid & 1;
    const int wn = wid >> 1;
    const int m0 = blockIdx.y * 128;
    const int n0 = blockIdx.x * 128;

    float acc[4][4][4];
#pragma unroll
    for (int mt = 0; mt < 4; mt++)
#pragma unroll
        for (int nt = 0; nt < 4; nt++)
#pragma unroll
            for (int q = 0; q < 4; q++) acc[mt][nt][q] = 0.f;

    const int lrow = tid >> 2, lseg = (tid & 3) * 8;

    const __nv_bfloat16* gp[4];
    gp[0] = Ahi + (size_t)m0 * 1024;
    gp[1] = Alo + (size_t)m0 * 1024;
    gp[2] = Bhi + (size_t)n0 * 1024;
    gp[3] = Blo + (size_t)n0 * 1024;

    auto load_chunk = [&](int kc, int buf) {
#pragma unroll
        for (int t = 0; t < 4; t++) {
            const __nv_bfloat16* g = gp[t] + kc * 32;
            uint32_t s = smem_u32(&dsm[buf * STAGE_E + t * TILE_E]);
            cpasync16(s + (lrow * GSTR + lseg) * 2, g + (size_t)lrow * 1024 + lseg);
            cpasync16(s + ((lrow + 64) * GSTR + lseg) * 2, g + (size_t)(lrow + 64) * 1024 + lseg);
        }
        CP_COMMIT();
    };

    const int r8 = lane & 7, sel = lane >> 3;

    load_chunk(0, 0);
    for (int kc = 0; kc < 32; kc++) {
        CP_WAIT0();
        __syncthreads();
        if (kc + 1 < 32) load_chunk(kc + 1, (kc + 1) & 1);
        const int buf = kc & 1;
        const uint32_t sAhi = smem_u32(&dsm[buf * STAGE_E + 0 * TILE_E]);
        const uint32_t sAlo = sAhi + TILE_E * 2;
        const uint32_t sBhi = sAhi + 2 * TILE_E * 2;
        const uint32_t sBlo = sAhi + 3 * TILE_E * 2;
#pragma unroll
        for (int ks = 0; ks < 2; ks++) {
            const int k16 = ks * 16;
            const int acol = k16 + (sel >> 1) * 8;
            const int bcol = k16 + (sel & 1) * 8;
            uint32_t ah[4][4], al[4][4], bb[2][4];
#pragma unroll
            for (int mt = 0; mt < 4; mt++) {
                int row = wm * 64 + mt * 16 + (sel & 1) * 8 + r8;
                ldsm4(ah[mt], sAhi + (row * GSTR + acol) * 2);
                ldsm4(al[mt], sAlo + (row * GSTR + acol) * 2);
            }
#pragma unroll
            for (int bt = 0; bt < 2; bt++) {
                int nrow = wn * 32 + bt * 16 + (sel >> 1) * 8 + r8;
                ldsm4(bb[bt], sBhi + (nrow * GSTR + bcol) * 2);
            }
#pragma unroll
            for (int mt = 0; mt < 4; mt++)
#pragma unroll
                for (int nt = 0; nt < 4; nt++) {
                    mma16816(acc[mt][nt], ah[mt], bb[nt >> 1][(nt & 1) * 2], bb[nt >> 1][(nt & 1) * 2 + 1]);
                    mma16816(acc[mt][nt], al[mt], bb[nt >> 1][(nt & 1) * 2], bb[nt >> 1][(nt & 1) * 2 + 1]);
                }
#pragma unroll
            for (int bt = 0; bt < 2; bt++) {
                int nrow = wn * 32 + bt * 16 + (sel >> 1) * 8 + r8;
                ldsm4(bb[bt], sBlo + (nrow * GSTR + bcol) * 2);
            }
#pragma unroll
            for (int mt = 0; mt < 4; mt++)
#pragma unroll
                for (int nt = 0; nt < 4; nt++)
                    mma16816(acc[mt][nt], ah[mt], bb[nt >> 1][(nt & 1) * 2], bb[nt >> 1][(nt & 1) * 2 + 1]);
        }
    }

    const int erow = lane >> 2, ecol = (lane & 3) * 2;
#pragma unroll
    for (int mt = 0; mt < 4; mt++) {
        const size_t row0 = (size_t)(m0 + wm * 64 + mt * 16 + erow);
#pragma unroll
        for (int nt = 0; nt < 4; nt++) {
            const size_t cb = (size_t)(n0 + wn * 32 + nt * 8 + ecol);
            *reinterpret_cast<float2*>(Cm + row0 * 1024 + cb) =
                make_float2(acc[mt][nt][0], acc[mt][nt][1]);
            *reinterpret_cast<float2*>(Cm + (row0 + 8) * 1024 + cb) =
                make_float2(acc[mt][nt][2], acc[mt][nt][3]);
        }
    }
}

__global__ void __launch_bounds__(256, 2) gemm_v_tc() { gemm_hmma_body(g_xhi, g_xlo, g_Wvhi, g_Wvlo, g_xwv); }
__global__ void __launch_bounds__(256, 2) gemm_g_tc() { gemm_hmma_body(g_xhi, g_xlo, g_Wghi, g_Wglo, g_gate); }
__global__ void __launch_bounds__(256, 2) gemm_o_tc(float* __restrict__ out) {
    gemm_hmma_body(g_ahi, g_alo, g_Wohi, g_Wolo, out);
}

// ---------------- causal depthwise conv + SiLU + beta (4 outputs/thread) --------
__global__ void __launch_bounds__(256) conv_silu(const float* __restrict__ conv_w,
                                                 const float* __restrict__ conv_b) {
    const int gb = blockIdx.x;
    const int dblk = gb & 3;
    const long tg = (long)(gb >> 2);
    const int d = dblk * 256 + threadIdx.x;
    const long bt0 = tg * 4;
    const int t0 = (int)(bt0 & (T_ - 1));
    const int h = d >> 7;

    float xr[7];
#pragma unroll
    for (int j = 0; j < 7; j++) {
        int tt = t0 - 3 + j;
        xr[j] = (tt >= 0) ? g_xwv[(bt0 - 3 + j) * D_ + d] : 0.f;
    }
    const float bs = conv_b[d];
    const float w0 = conv_w[d * 4 + 0], w1 = conv_w[d * 4 + 1];
    const float w2 = conv_w[d * 4 + 2], w3 = conv_w[d * 4 + 3];
#pragma unroll
    for (int i = 0; i < 4; i++) {
        float a = bs;
        a = fmaf(xr[i + 0], w0, a);
        a = fmaf(xr[i + 1], w1, a);
        a = fmaf(xr[i + 2], w2, a);
        a = fmaf(xr[i + 3], w3, a);
        float s = a / (1.f + __expf(-a));
        g_v[(bt0 + i) * D_ + d] = s * g_beta[(bt0 + i) * H_ + h];
    }
}

// ---------------- per-chunk: cumsum, HMMA dots, attn(bf16), blocked solve --------
__global__ void __launch_bounds__(256, 2) chunk_prep() {
    extern __shared__ char cpsm[];
    __nv_bfloat16* swh = (__nv_bfloat16*)cpsm;             // 64*CAB
    __nv_bfloat16* swl = swh + 64 * CAB;
    __nv_bfloat16* srh = swl + 64 * CAB;
    __nv_bfloat16* srl = srh + 64 * CAB;                   // end 69632 B
    float* sA = (float*)(cpsm + 69632);                    // 64*64 fp32 -> end 86016 B
    float* s1 = (float*)(cpsm + 34816);                    // aliases srh/srl
    float* s2 = (float*)cpsm;                              // aliases swh/swl
    __shared__ float sdec[C_], sbeta[C_], sraw[C_];
    const int id = blockIdx.x;
    const int chunk = id & 63;
    const int bh = id >> 6;
    const int b = bh >> 3, h = bh & 7;
    const long t0 = (long)b * T_ + chunk * C_;
    const long base = t0 * D_ + h * K_;
    const int tid = threadIdx.x;
    const int wid = tid >> 5, lane = tid & 31;
    const int g8 = lane >> 3, r8 = lane & 7;

    {
        const uint32_t swh_s = smem_u32(swh), swl_s = smem_u32(swl);
        const uint32_t srh_s = smem_u32(srh), srl_s = smem_u32(srl);
#pragma unroll
        for (int q = 0; q < 4; q++) {
            int u = tid + q * 256;
            int row = u >> 4, seg = (u & 15) * 8;
            uint32_t d = (uint32_t)(row * CAB + seg) * 2;
            long g = base + (long)row * D_ + seg;
            cpasync16(swh_s + d, g_wk_h + g);
            cpasync16(swl_s + d, g_wk_l + g);
            cpasync16(srh_s + d, g_rk_h + g);
            cpasync16(srl_s + d, g_rk_l + g);
        }
        CP_COMMIT();
    }
    if (tid < C_) {
        sraw[tid] = g_dec[(t0 + tid) * H_ + h];
        sbeta[tid] = g_beta[(t0 + tid) * H_ + h];
    }
    __syncthreads();
    if (tid < C_) {
        float acc = 0.f;
        for (int j = 0; j <= tid; j++) acc += sraw[j];
        sdec[tid] = acc;
        g_dcum[(t0 + tid) * H_ + h] = acc;
    }
    CP_WAIT0();
    __syncthreads();

    // HMMA: P = [wk; rk] @ wk^T
    {
        const uint32_t swh_s = smem_u32(swh), swl_s = smem_u32(swl);
        const uint32_t srh_s = smem_u32(srh), srl_s = smem_u32(srl);
        const uint32_t ash = (wid < 4) ? swh_s : srh_s;
        const uint32_t asl = (wid < 4) ? swl_s : srl_s;
        const int am0 = (wid & 3) * 16;
        const int aro = (g8 & 1) * 8 + r8, aco = (g8 >> 1) * 8;
        const int bro = (g8 >> 1) * 8 + r8, bco = (g8 & 1) * 8;
        float acc[8][4];
#pragma unroll
        for (int nt = 0; nt < 8; nt++)
#pragma unroll
            for (int q = 0; q < 4; q++) acc[nt][q] = 0.f;
#pragma unroll
        for (int ks = 0; ks < 8; ks++) {
            uint32_t ah[4], al[4], bh4[4][4], bl4[4][4];
            uint32_t aoff = (uint32_t)((am0 + aro) * CAB + ks * 16 + aco) * 2;
            ldsm4(ah, ash + aoff);
            ldsm4(al, asl + aoff);
#pragma unroll
            for (int bt = 0; bt < 4; bt++) {
                uint32_t boff = (uint32_t)((bt * 16 + bro) * CAB + ks * 16 + bco) * 2;
                ldsm4(bh4[bt], swh_s + boff);
                ldsm4(bl4[bt], swl_s + boff);
            }
#pragma unroll
            for (int nt = 0; nt < 8; nt++) {
                uint32_t b0h = bh4[nt >> 1][(nt & 1) * 2], b1h = bh4[nt >> 1][(nt & 1) * 2 + 1];
                uint32_t b0l = bl4[nt >> 1][(nt & 1) * 2], b1l = bl4[nt >> 1][(nt & 1) * 2 + 1];
                mma16816(acc[nt], ah, b0h, b1h);
                mma16816(acc[nt], al, b0h, b1h);
                mma16816(acc[nt], ah, b0l, b1l);
            }
        }
        const int er = lane >> 2, ec = (lane & 3) * 2;
        const int i1 = am0 + er, i2 = i1 + 8;
        if (wid < 4) {
            const float b1v = sbeta[i1], b2v = sbeta[i2];
            const float d1 = sdec[i1], d2 = sdec[i2];
#pragma unroll
            for (int nt = 0; nt < 8; nt++) {
                const int j = nt * 8 + ec;
                float a00 = (j     < i1) ? -acc[nt][0] * b1v * __expf(d1 - sdec[j])     : 0.f;
                float a01 = (j + 1 < i1) ? -acc[nt][1] * b1v * __expf(d1 - sdec[j + 1]) : 0.f;
                float a10 = (j     < i2) ? -acc[nt][2] * b2v * __expf(d2 - sdec[j])     : 0.f;
                float a11 = (j + 1 < i2) ? -acc[nt][3] * b2v * __expf(d2 - sdec[j + 1]) : 0.f;
                sA[i1 * 64 + j] = a00; sA[i1 * 64 + j + 1] = a01;
                sA[i2 * 64 + j] = a10; sA[i2 * 64 + j + 1] = a11;
            }
        } else {
            const float d1 = sdec[i1], d2 = sdec[i2];
            const long ab = (long)id * 4096;
#pragma unroll
            for (int nt = 0; nt < 8; nt++) {
                const int j = nt * 8 + ec;
                float a00 = (j     <= i1) ? acc[nt][0] * __expf(d1 - sdec[j])     : 0.f;
                float a01 = (j + 1 <= i1) ? acc[nt][1] * __expf(d1 - sdec[j + 1]) : 0.f;
                float a10 = (j     <= i2) ? acc[nt][2] * __expf(d2 - sdec[j])     : 0.f;
                float a11 = (j + 1 <= i2) ? acc[nt][3] * __expf(d2 - sdec[j + 1]) : 0.f;
                __nv_bfloat16 h0, l0, h1, l1;
                bfsplit(a00, h0, l0); bfsplit(a01, h1, l1);
                *reinterpret_cast<__nv_bfloat162*>(g_attn_h + ab + i1 * 64 + j) = __nv_bfloat162(h0, h1);
                *reinterpret_cast<__nv_bfloat162*>(g_attn_l + ab + i1 * 64 + j) = __nv_bfloat162(l0, l1);
                bfsplit(a10, h0, l0); bfsplit(a11, h1, l1);
                *reinterpret_cast<__nv_bfloat162*>(g_attn_h + ab + i2 * 64 + j) = __nv_bfloat162(h0, h1);
                *reinterpret_cast<__nv_bfloat162*>(g_attn_l + ab + i2 * 64 + j) = __nv_bfloat162(l0, l1);
            }
        }
    }
    if (tid < C_) sraw[tid] = sbeta[tid] * __expf(sdec[tid]);
    __syncthreads();

    for (int i = tid; i < C_ * K_; i += 256) {
        int c = i >> 7, k = i & 127;
        float wv = __bfloat162float(swh[c * CAB + k]) + __bfloat162float(swl[c * CAB + k]);
        s1[c * RS + k] = wv * sraw[c];
    }
    __syncthreads();
    for (int i = tid; i < C_ * K_; i += 256) {
        int c = i >> 7, k = i & 127;
        s2[c * RS + k] = g_v[base + (long)c * D_ + k];
    }
    __syncthreads();

    {
        float* sx = (tid < 128) ? s1 : s2;
        const int k = tid & 127;
        for (int i = 1; i < 32; i++) {
            float a = 0.f;
            const float* Ai = sA + i * 64;
#pragma unroll 4
            for (int j = 0; j < i; j++)
                a = fmaf(Ai[j], sx[j * RS + k], a);
            sx[i * RS + k] += a;
        }
        float up[32];
#pragma unroll
        for (int i = 0; i < 32; i++) up[i] = 0.f;
        for (int j = 0; j < 32; j++) {
            float xv = sx[j * RS + k];
#pragma unroll
            for (int i = 0; i < 32; i++)
                up[i] = fmaf(sA[(32 + i) * 64 + j], xv, up[i]);
        }
#pragma unroll
        for (int i = 0; i < 32; i++)
            sx[(32 + i) * RS + k] += up[i];
        for (int i = 33; i < 64; i++) {
            float a = 0.f;
            const float* Ai = sA + i * 64;
#pragma unroll 4
            for (int j = 32; j < i; j++)
                a = fmaf(Ai[j], sx[j * RS + k], a);
            sx[i * RS + k] += a;
        }
    }
    __syncthreads();

    for (int i = tid; i < C_ * K_; i += 256) {
        int c = i >> 7, k = i & 127;
        float u = s1[c * RS + k];
        __nv_bfloat16 hh, ll;
        bfsplit(u, hh, ll);
        g_wkc_h[base + (long)c * D_ + k] = hh;
        g_wkc_l[base + (long)c * D_ + k] = ll;
        g_v[base + (long)c * D_ + k] = s2[c * RS + k];
    }
}

// ---------------- HMMA chunk scan: 512 threads, N split across warp groups -------
#define SHS 56     // Shi/Slo, svh/svl, s2h/l bf16
#define SAB 136    // sA / swk bf16
#define STB 72     // attn bf16
#define SVF 36     // sv fp32

__global__ void __launch_bounds__(512) scan_kernel() {
    extern __shared__ char smraw[];
    __nv_bfloat16* sShi = (__nv_bfloat16*)smraw;
    __nv_bfloat16* sSlo = sShi + 128 * SHS;
    __nv_bfloat16* sAh  = sSlo + 128 * SHS;
    __nv_bfloat16* sAl  = sAh + 128 * SAB;
    __nv_bfloat16* sWh  = sAl + 128 * SAB;
    __nv_bfloat16* sWl  = sWh + 64 * SAB;
    __nv_bfloat16* sTh  = sWl + 64 * SAB;
    __nv_bfloat16* sTl  = sTh + 64 * STB;
    __nv_bfloat16* svh  = sTl + 64 * STB;
    __nv_bfloat16* svl  = svh + 64 * SHS;
    __nv_bfloat16* s2h  = svl + 64 * SHS;
    __nv_bfloat16* s2l  = s2h + 64 * SHS;
    float* sv = (float*)(s2l + 64 * SHS);

    const int bh = blockIdx.x >> 2;
    const int slice = blockIdx.x & 3;
    const int b = bh >> 3, h = bh & 7;
    const int j0g = slice * SW;
    const int tid = threadIdx.x;
    const int wid = tid >> 5, lane = tid & 31;
    const int wrow = wid & 7;                 // row-group
    const int nhb = (wid >> 3) * 16;          // n-half column base (0 or 16)
    const int g8 = lane >> 3, r8 = lane & 7;
    const int aro = (g8 & 1) * 8 + r8;
    const int aco = (g8 >> 1) * 8;
    const int bro = (g8 & 1) * 8 + r8;
    const int bco = (g8 >> 1) * 8;
    const int tro = (g8 >> 1) * 8 + r8;
    const int tco = (g8 & 1) * 8;
    const int er = lane >> 2, ec = (lane & 3) * 2;
    // group-local linear tid for W/T prefetch (S-group = wid {0-3,8-11}, O-group = {4-7,12-15})
    const int glt = (((wid & 3) | ((wid >> 3) << 2)) << 5) + lane;   // 0..255 within group
    const bool sgrp = (wid & 4) == 0;

    const uint32_t sShi_s = smem_u32(sShi), sSlo_s = smem_u32(sSlo);
    const uint32_t sAh_s = smem_u32(sAh), sAl_s = smem_u32(sAl);
    const uint32_t sWh_s = smem_u32(sWh), sWl_s = smem_u32(sWl);
    const uint32_t sTh_s = smem_u32(sTh), sTl_s = smem_u32(sTl);
    const uint32_t svh_s = smem_u32(svh), svl_s = smem_u32(svl);
    const uint32_t s2h_s = smem_u32(s2h), s2l_s = smem_u32(s2l);
    const uint32_t sv_s = smem_u32(sv);

    auto issue_Av = [&](int chunk) {
        const long base = ((long)b * T_ + chunk * C_) * D_ + h * K_;
#pragma unroll
        for (int q = 0; q < 4; q++) {
            int u = tid + q * 512;            // 0..2047
            int row = u >> 4, seg = (u & 15) * 8;
            uint32_t d = (uint32_t)(row * SAB + seg) * 2;
            if (row < 64) {
                long g = base + (long)row * D_ + seg;
                cpasync16(sAh_s + d, g_wkc_h + g);
                cpasync16(sAl_s + d, g_wkc_l + g);
            } else {
                long g = base + (long)(row - 64) * D_ + seg;
                cpasync16(sAh_s + d, g_rk_h + g);
                cpasync16(sAl_s + d, g_rk_l + g);
            }
        }
        {
            int u = tid;                      // 0..511
            int row = u >> 3, seg = (u & 7) * 4;
            cpasync16(sv_s + (uint32_t)(row * SVF + seg) * 4,
                      g_v + base + (long)row * D_ + j0g + seg);
        }
        CP_COMMIT();
    };
    auto issue_W = [&](int chunk) {           // S-group (256 threads)
        const long base = ((long)b * T_ + chunk * C_) * D_ + h * K_;
#pragma unroll
        for (int q = 0; q < 4; q++) {
            int u = glt + q * 256;            // 0..1023
            int row = u >> 4, seg = (u & 15) * 8;
            uint32_t d = (uint32_t)(row * SAB + seg) * 2;
            long g = base + (long)row * D_ + seg;
            cpasync16(sWh_s + d, g_wk_h + g);
            cpasync16(sWl_s + d, g_wk_l + g);
        }
        CP_COMMIT();
    };
    auto issue_T = [&](int chunk) {           // O-group (256 threads)
        const long ab = ((long)bh * NCH + chunk) * 4096;
#pragma unroll
        for (int q = 0; q < 2; q++) {
            int u = glt + q * 256;            // 0..511
            int row = u >> 3, seg = (u & 7) * 8;
            uint32_t d = (uint32_t)(row * STB + seg) * 2;
            cpasync16(sTh_s + d, g_attn_h + ab + row * 64 + seg);
            cpasync16(sTl_s + d, g_attn_l + ab + row * 64 + seg);
        }
        CP_COMMIT();
    };

    // fp32 master S in registers of S-group warps: rows wrow*32..+32, cols nhb..nhb+16
    float Sreg[2][8];
#pragma unroll
    for (int mt = 0; mt < 2; mt++)
#pragma unroll
        for (int q = 0; q < 8; q++) Sreg[mt][q] = 0.f;

    for (int i = tid; i < 128 * SHS; i += 512) {
        sShi[i] = __float2bfloat16(0.f);
        sSlo[i] = __float2bfloat16(0.f);
    }
    issue_Av(0);
    if (sgrp) issue_W(0); else issue_T(0);

    const int m0 = wrow * 16;

    for (int chunk = 0; chunk < NCH; chunk++) {
        const long t0 = (long)b * T_ + chunk * C_;
        const long obase = t0 * D_ + h * K_;
        CP_WAIT0();
        const int myrow = (wid & 3) * 16 + er;
        const float dec63 = g_dcum[(t0 + 63) * H_ + h];
        const float decA = g_dcum[(t0 + myrow) * H_ + h];
        const float decB = g_dcum[(t0 + myrow + 8) * H_ + h];
        __syncthreads();

        // ---- HMMA1: P(128x32) = [wkc; rk] @ S ; this warp: rows m0..+16, cols nhb..+16
        float acc[2][4];
#pragma unroll
        for (int nt = 0; nt < 2; nt++)
#pragma unroll
            for (int q = 0; q < 4; q++) acc[nt][q] = 0.f;
#pragma unroll
        for (int ks = 0; ks < 8; ks++) {
            uint32_t ah[4], al[4], bhf[4], blf[4];
            uint32_t aoff = (uint32_t)((m0 + aro) * SAB + ks * 16 + aco) * 2;
            ldsm4(ah, sAh_s + aoff);
            ldsm4(al, sAl_s + aoff);
            uint32_t boff = (uint32_t)((ks * 16 + bro) * SHS + nhb + bco) * 2;
            ldsm4t(bhf, sShi_s + boff);
            ldsm4t(blf, sSlo_s + boff);
#pragma unroll
            for (int nt = 0; nt < 2; nt++) {
                uint32_t b0h = bhf[nt * 2], b1h = bhf[nt * 2 + 1];
                uint32_t b0l = blf[nt * 2], b1l = blf[nt * 2 + 1];
                mma16816(acc[nt], ah, b0h, b1h);
                mma16816(acc[nt], al, b0h, b1h);
                mma16816(acc[nt], ah, b0l, b1l);
            }
        }

        // ---- epilogue 1 ----
        if (sgrp) {
            const int c1 = m0 + er, c2 = c1 + 8;
            const float dw1 = __expf(dec63 - decA), dw2 = __expf(dec63 - decB);
#pragma unroll
            for (int nt = 0; nt < 2; nt++) {
                const int col = nhb + nt * 8 + ec;
                float a0 = sv[c1 * SVF + col]     - acc[nt][0];
                float a1 = sv[c1 * SVF + col + 1] - acc[nt][1];
                float a2 = sv[c2 * SVF + col]     - acc[nt][2];
                float a3 = sv[c2 * SVF + col + 1] - acc[nt][3];
                __nv_bfloat16 h0, l0, h1, l1, h2, l2, h3, l3;
                bfsplit(a0, h0, l0); bfsplit(a1, h1, l1);
                bfsplit(a2, h2, l2); bfsplit(a3, h3, l3);
                *reinterpret_cast<__nv_bfloat162*>(svh + c1 * SHS + col) = __nv_bfloat162(h0, h1);
                *reinterpret_cast<__nv_bfloat162*>(svl + c1 * SHS + col) = __nv_bfloat162(l0, l1);
                *reinterpret_cast<__nv_bfloat162*>(svh + c2 * SHS + col) = __nv_bfloat162(h2, h3);
                *reinterpret_cast<__nv_bfloat162*>(svl + c2 * SHS + col) = __nv_bfloat162(l2, l3);
                float b0 = dw1 * a0, b1 = dw1 * a1, b2 = dw2 * a2, b3 = dw2 * a3;
                bfsplit(b0, h0, l0); bfsplit(b1, h1, l1);
                bfsplit(b2, h2, l2); bfsplit(b3, h3, l3);
                *reinterpret_cast<__nv_bfloat162*>(s2h + c1 * SHS + col) = __nv_bfloat162(h0, h1);
                *reinterpret_cast<__nv_bfloat162*>(s2l + c1 * SHS + col) = __nv_bfloat162(l0, l1);
                *reinterpret_cast<__nv_bfloat162*>(s2h + c2 * SHS + col) = __nv_bfloat162(h2, h3);
                *reinterpret_cast<__nv_bfloat162*>(s2l + c2 * SHS + col) = __nv_bfloat162(l2, l3);
            }
        } else {
            const float e1 = __expf(decA), e2 = __expf(decB);
#pragma unroll
            for (int nt = 0; nt < 2; nt++) {
                acc[nt][0] *= e1; acc[nt][1] *= e1;
                acc[nt][2] *= e2; acc[nt][3] *= e2;
            }
        }
        __syncthreads();
        if (chunk + 1 < NCH) issue_Av(chunk + 1);

        if (!sgrp) {
            // ---- o = e*rkS (in acc) + attn @ v_new ----
            const int m0o = (wrow - 4) * 16;
#pragma unroll
            for (int ks = 0; ks < 4; ks++) {
                uint32_t ah[4], al[4], bhf[4], blf[4];
                uint32_t aoff = (uint32_t)((m0o + aro) * STB + ks * 16 + aco) * 2;
                ldsm4(ah, sTh_s + aoff);
                ldsm4(al, sTl_s + aoff);
                uint32_t boff = (uint32_t)((ks * 16 + bro) * SHS + nhb + bco) * 2;
                ldsm4t(bhf, svh_s + boff);
                ldsm4t(blf, svl_s + boff);
#pragma unroll
                for (int nt = 0; nt < 2; nt++) {
                    uint32_t b0h = bhf[nt * 2], b1h = bhf[nt * 2 + 1];
                    uint32_t b0l = blf[nt * 2], b1l = blf[nt * 2 + 1];
                    mma16816(acc[nt], ah, b0h, b1h);
                    mma16816(acc[nt], al, b0h, b1h);
                    mma16816(acc[nt], ah, b0l, b1l);
                }
            }
            const int c1 = m0o + er, c2 = c1 + 8;
#pragma unroll
            for (int nt = 0; nt < 2; nt++) {
                const int col = nhb + nt * 8 + ec;
                *reinterpret_cast<float2*>(g_o + obase + (long)c1 * D_ + j0g + col) =
                    make_float2(acc[nt][0], acc[nt][1]);
                *reinterpret_cast<float2*>(g_o + obase + (long)c2 * D_ + j0g + col) =
                    make_float2(acc[nt][2], acc[nt][3]);
            }
            if (chunk + 1 < NCH) issue_T(chunk + 1);
        } else {
            // ---- S = e63*S + wk^T @ (dw*v_new), in registers; write Shi/Slo ----
            const float e63 = __expf(dec63);
#pragma unroll
            for (int mt = 0; mt < 2; mt++) {
                const int m0s = wrow * 32 + mt * 16;
                float a2c[2][4];
#pragma unroll
                for (int nt = 0; nt < 2; nt++)
#pragma unroll
                    for (int q = 0; q < 4; q++) a2c[nt][q] = 0.f;
#pragma unroll
                for (int ks = 0; ks < 4; ks++) {
                    uint32_t ah[4], al[4], bhf[4], blf[4];
                    uint32_t aoff = (uint32_t)((ks * 16 + tro) * SAB + m0s + tco) * 2;
                    ldsm4t(ah, sWh_s + aoff);
                    ldsm4t(al, sWl_s + aoff);
                    uint32_t boff = (uint32_t)((ks * 16 + bro) * SHS + nhb + bco) * 2;
                    ldsm4t(bhf, s2h_s + boff);
                    ldsm4t(blf, s2l_s + boff);
#pragma unroll
                    for (int nt = 0; nt < 2; nt++) {
                        uint32_t b0h = bhf[nt * 2], b1h = bhf[nt * 2 + 1];
                        uint32_t b0l = blf[nt * 2], b1l = blf[nt * 2 + 1];
                        mma16816(a2c[nt], ah, b0h, b1h);
                        mma16816(a2c[nt], al, b0h, b1h);
                        mma16816(a2c[nt], ah, b0l, b1l);
                    }
                }
                const int k1 = m0s + er, k2 = k1 + 8;
#pragma unroll
                for (int nt = 0; nt < 2; nt++) {
                    const int col = nhb + nt * 8 + ec;
                    float n00 = Sreg[mt][nt * 4 + 0] * e63 + a2c[nt][0];
                    float n01 = Sreg[mt][nt * 4 + 1] * e63 + a2c[nt][1];
                    float n10 = Sreg[mt][nt * 4 + 2] * e63 + a2c[nt][2];
                    float n11 = Sreg[mt][nt * 4 + 3] * e63 + a2c[nt][3];
                    Sreg[mt][nt * 4 + 0] = n00; Sreg[mt][nt * 4 + 1] = n01;
                    Sreg[mt][nt * 4 + 2] = n10; Sreg[mt][nt * 4 + 3] = n11;
                    __nv_bfloat16 hh, ll;
                    bfsplit(n00, hh, ll); sShi[k1 * SHS + col] = hh;     sSlo[k1 * SHS + col] = ll;
                    bfsplit(n01, hh, ll); sShi[k1 * SHS + col + 1] = hh; sSlo[k1 * SHS + col + 1] = ll;
                    bfsplit(n10, hh, ll); sShi[k2 * SHS + col] = hh;     sSlo[k2 * SHS + col] = ll;
                    bfsplit(n11, hh, ll); sShi[k2 * SHS + col + 1] = hh; sSlo[k2 * SHS + col + 1] = ll;
                }
            }
            if (chunk + 1 < NCH) issue_W(chunk + 1);
        }
    }
}

// ---------------- per-head RMSNorm + gated SiLU (warp per row) -------------------
__global__ void __launch_bounds__(256) rms_gate(const float* __restrict__ norm_w) {
    const int row = blockIdx.x * 8 + (threadIdx.x >> 5);
    const int lane = threadIdx.x & 31;
    const long gi = (long)row * K_ + lane * 4;
    float4 ov = *reinterpret_cast<const float4*>(g_o + gi);
    float s = ov.x * ov.x + ov.y * ov.y + ov.z * ov.z + ov.w * ov.w;
#pragma unroll
    for (int off = 16; off; off >>= 1) s += __shfl_xor_sync(0xffffffffu, s, off);
    float r = rsqrtf(s * (1.f / 128.f) + 1e-5f);
    float4 g = *reinterpret_cast<const float4*>(g_gate + gi);
    float4 nw = *reinterpret_cast<const float4*>(norm_w + lane * 4);
    float v0 = ov.x * r * nw.x * (g.x / (1.f + __expf(-g.x)));
    float v1 = ov.y * r * nw.y * (g.y / (1.f + __expf(-g.y)));
    float v2 = ov.z * r * nw.z * (g.z / (1.f + __expf(-g.z)));
    float v3 = ov.w * r * nw.w * (g.w / (1.f + __expf(-g.w)));
    __nv_bfloat16 h0, l0, h1, l1, h2, l2, h3, l3;
    bfsplit(v0, h0, l0); bfsplit(v1, h1, l1);
    bfsplit(v2, h2, l2); bfsplit(v3, h3, l3);
    *reinterpret_cast<__nv_bfloat162*>(g_ahi + gi)     = __nv_bfloat162(h0, h1);
    *reinterpret_cast<__nv_bfloat162*>(g_ahi + gi + 2) = __nv_bfloat162(h2, h3);
    *reinterpret_cast<__nv_bfloat162*>(g_alo + gi)     = __nv_bfloat162(l0, l1);
    *reinterpret_cast<__nv_bfloat162*>(g_alo + gi + 2) = __nv_bfloat162(l2, l3);
}

// ---------------- launcher ------------------------------------------------------
extern "C" void kernel_launch(void* const* d_in, const int* in_sizes, int n_in,
                              void* d_out, int out_size) {
    const float* x       = (const float*)d_in[0];
    const float* Wv      = (const float*)d_in[1];
    const float* Wg      = (const float*)d_in[2];
    const float* Wo      = (const float*)d_in[3];
    const float* Wb      = (const float*)d_in[4];
    const float* Wa      = (const float*)d_in[5];
    const float* dt_bias = (const float*)d_in[6];
    const float* A_log   = (const float*)d_in[7];
    const float* norm_w  = (const float*)d_in[8];
    const float* conv_w  = (const float*)d_in[9];
    const float* conv_b  = (const float*)d_in[10];
    float* out = (float*)d_out;

    const int CP_SMEM   = 86016;
    const int SCAN_SMEM = (2 * 128 * SHS + 2 * 128 * SAB + 2 * 64 * SAB +
                           2 * 64 * STB + 4 * 64 * SHS) * 2 + 64 * SVF * 4;
    const int GEMM_SMEM = 2 * STAGE_E * 2;
    cudaFuncSetAttribute(chunk_prep,  cudaFuncAttributeMaxDynamicSharedMemorySize, CP_SMEM);
    cudaFuncSetAttribute(scan_kernel, cudaFuncAttributeMaxDynamicSharedMemorySize, SCAN_SMEM);
    cudaFuncSetAttribute(gemm_v_tc,   cudaFuncAttributeMaxDynamicSharedMemorySize, GEMM_SMEM);
    cudaFuncSetAttribute(gemm_g_tc,   cudaFuncAttributeMaxDynamicSharedMemorySize, GEMM_SMEM);
    cudaFuncSetAttribute(gemm_o_tc,   cudaFuncAttributeMaxDynamicSharedMemorySize, GEMM_SMEM);

    dim3 gg(D_ / 128, M_ / 128);

    if (s_ok) {
        cudaEventRecord(ev_root, 0);
        cudaStreamWaitEvent(s_aux2, ev_root, 0);
        split_w_k<<<(3 * D_ * D_) / 1024, 256, 0, s_aux2>>>(Wv, Wg, Wo);
        cudaEventRecord(ev_w, s_aux2);
        prep_tokens<<<M_, 256>>>(x, Wb, Wa, dt_bias, A_log);
        cudaEventRecord(ev_p, 0);
        cudaStreamWaitEvent(s_aux1, ev_w, 0);
        cudaStreamWaitEvent(s_aux1, ev_p, 0);
        gemm_g_tc<<<gg, 256, GEMM_SMEM, s_aux1>>>();
        cudaEventRecord(ev_g, s_aux1);
        cudaStreamWaitEvent(0, ev_w, 0);
        gemm_v_tc<<<gg, 256, GEMM_SMEM>>>();
        conv_silu<<<(B_ * T_ / 4) * (D_ / 256), 256>>>(conv_w, conv_b);
        chunk_prep<<<B_ * H_ * NCH, 256, CP_SMEM>>>();
        scan_kernel<<<B_ * H_ * SLICES, 512, SCAN_SMEM>>>();
        cudaStreamWaitEvent(0, ev_g, 0);
        rms_gate<<<M_ * H_ / 8, 256>>>(norm_w);
        gemm_o_tc<<<gg, 256, GEMM_SMEM>>>(out);
    } else {
        prep_tokens<<<M_, 256>>>(x, Wb, Wa, dt_bias, A_log);
        split_w_k<<<(3 * D_ * D_) / 1024, 256>>>(Wv, Wg, Wo);
        gemm_v_tc<<<gg, 256, GEMM_SMEM>>>();
        gemm_g_tc<<<gg, 256, GEMM_SMEM>>>();
        conv_silu<<<(B_ * T_ / 4) * (D_ / 256), 256>>>(conv_w, conv_b);
        chunk_prep<<<B_ * H_ * NCH, 256, CP_SMEM>>>();
        scan_kernel<<<B_ * H_ * SLICES, 512, SCAN_SMEM>>>();
        rms_gate<<<M_ * H_ / 8, 256>>>(norm_w);
        gemm_o_tc<<<gg, 256, GEMM_SMEM>>>(out);
    }
}

// round 14
// speedup vs baseline: 1.0069x; 1.0069x over previous
#include <cuda_runtime.h>
#include <cuda_bf16.h>
#include <math.h>
#include <cstdint>

#define B_ 4
#define T_ 4096
#define D_ 1024
#define H_ 8
#define K_ 128
#define C_ 64
#define NCH 64
#define M_ (B_*T_)
#define RS 129
#define SLICES 4
#define SW 32
#define GSTR 40           // bf16 smem stride for GEMM tiles
#define CAB 136           // chunk_prep bf16 tile stride

// ---------------- scratch -------------------------------------------------------
__device__ float g_xwv [B_*T_*D_];
__device__ float g_gate[B_*T_*D_];
__device__ float g_v   [B_*T_*D_];
__device__ float g_o   [B_*T_*D_];
__device__ float g_beta[B_*T_*H_];
__device__ float g_dec [B_*T_*H_];
__device__ float g_dcum[B_*T_*H_];
__device__ __nv_bfloat16 g_attn_h[B_*H_*NCH*C_*C_], g_attn_l[B_*H_*NCH*C_*C_];
__device__ __nv_bfloat16 g_rk_h [M_*D_], g_rk_l [M_*D_];
__device__ __nv_bfloat16 g_wk_h [M_*D_], g_wk_l [M_*D_];
__device__ __nv_bfloat16 g_wkc_h[M_*D_], g_wkc_l[M_*D_];
__device__ __nv_bfloat16 g_xhi[M_*D_], g_xlo[M_*D_];
__device__ __nv_bfloat16 g_ahi[M_*D_], g_alo[M_*D_];
__device__ __nv_bfloat16 g_Wvhi[D_*D_], g_Wvlo[D_*D_];
__device__ __nv_bfloat16 g_Wghi[D_*D_], g_Wglo[D_*D_];
__device__ __nv_bfloat16 g_Wohi[D_*D_], g_Wolo[D_*D_];

// ---------------- streams/events for graph-captured fork -------------------------
static cudaStream_t s_aux1 = nullptr, s_aux2 = nullptr;
static cudaEvent_t ev_root = nullptr, ev_w = nullptr, ev_p = nullptr, ev_g = nullptr;
static bool s_ok = false;
struct _StreamInit {
    _StreamInit() {
        s_ok = (cudaStreamCreateWithFlags(&s_aux1, cudaStreamNonBlocking) == cudaSuccess) &&
               (cudaStreamCreateWithFlags(&s_aux2, cudaStreamNonBlocking) == cudaSuccess) &&
               (cudaEventCreateWithFlags(&ev_root, cudaEventDisableTiming) == cudaSuccess) &&
               (cudaEventCreateWithFlags(&ev_w, cudaEventDisableTiming) == cudaSuccess) &&
               (cudaEventCreateWithFlags(&ev_p, cudaEventDisableTiming) == cudaSuccess) &&
               (cudaEventCreateWithFlags(&ev_g, cudaEventDisableTiming) == cudaSuccess);
    }
};
static _StreamInit _stream_init_obj;

// ================= low-level helpers ===========================================
__device__ __forceinline__ uint32_t smem_u32(const void* p) {
    uint32_t a;
    asm("{ .reg .u64 t; cvta.to.shared.u64 t, %1; cvt.u32.u64 %0, t; }" : "=r"(a) : "l"(p));
    return a;
}
__device__ __forceinline__ void cpasync16(uint32_t saddr, const void* gaddr) {
    asm volatile("cp.async.cg.shared.global [%0], [%1], 16;" :: "r"(saddr), "l"(gaddr));
}
#define CP_COMMIT() asm volatile("cp.async.commit_group;" ::: "memory")
#define CP_WAIT0()  asm volatile("cp.async.wait_group 0;" ::: "memory")

__device__ __forceinline__ void ldsm4(uint32_t* r, uint32_t saddr) {
    asm volatile("ldmatrix.sync.aligned.m8n8.x4.shared.b16 {%0,%1,%2,%3}, [%4];"
        : "=r"(r[0]), "=r"(r[1]), "=r"(r[2]), "=r"(r[3]) : "r"(saddr));
}
__device__ __forceinline__ void ldsm4t(uint32_t* r, uint32_t saddr) {
    asm volatile("ldmatrix.sync.aligned.m8n8.x4.trans.shared.b16 {%0,%1,%2,%3}, [%4];"
        : "=r"(r[0]), "=r"(r[1]), "=r"(r[2]), "=r"(r[3]) : "r"(saddr));
}
__device__ __forceinline__ void mma16816(float* c, const uint32_t* a, uint32_t b0, uint32_t b1) {
    asm volatile(
        "mma.sync.aligned.m16n8k16.row.col.f32.bf16.bf16.f32 "
        "{%0,%1,%2,%3}, {%4,%5,%6,%7}, {%8,%9}, {%0,%1,%2,%3};"
        : "+f"(c[0]), "+f"(c[1]), "+f"(c[2]), "+f"(c[3])
        : "r"(a[0]), "r"(a[1]), "r"(a[2]), "r"(a[3]), "r"(b0), "r"(b1));
}
__device__ __forceinline__ void bfsplit(float v, __nv_bfloat16& h, __nv_bfloat16& l) {
    h = __float2bfloat16(v);
    l = __float2bfloat16(v - __bfloat162float(h));
}

// ================= fused token prep (4 rows per block, x read once) =============
__global__ void __launch_bounds__(256) prep_tokens(const float* __restrict__ x,
                                                   const float* __restrict__ Wb,
                                                   const float* __restrict__ Wa,
                                                   const float* __restrict__ dt_bias,
                                                   const float* __restrict__ A_log) {
    const int r0 = blockIdx.x * 4;          // 4 consecutive rows, same batch (T%4==0)
    const int t0 = r0 & (T_ - 1);
    __shared__ float sm[5][D_];
    const int tid = threadIdx.x;
    // load rows r0-1 .. r0+3 (rr=0 is prev-of-first; zero at batch start)
#pragma unroll
    for (int rr = 0; rr < 5; rr++) {
        float4 v;
        if (rr == 0 && t0 == 0) v = make_float4(0.f, 0.f, 0.f, 0.f);
        else v = reinterpret_cast<const float4*>(x + ((long)r0 - 1 + rr) * D_)[tid];
        reinterpret_cast<float4*>(sm[rr])[tid] = v;
    }
    __syncthreads();

    const int w = tid >> 5, lane = tid & 31;

#pragma unroll
    for (int i = 0; i < 4; i++) {
        const int row = r0 + i;
        float* sx = sm[i + 1];
        float* sxp = sm[i];

        // x splits
        {
            float4 v = reinterpret_cast<float4*>(sx)[tid];
            long gi = (long)row * D_ + tid * 4;
            __nv_bfloat16 h0, h1, h2, h3, l0, l1, l2, l3;
            bfsplit(v.x, h0, l0); bfsplit(v.y, h1, l1);
            bfsplit(v.z, h2, l2); bfsplit(v.w, h3, l3);
            *reinterpret_cast<__nv_bfloat162*>(g_xhi + gi)     = __nv_bfloat162(h0, h1);
            *reinterpret_cast<__nv_bfloat162*>(g_xhi + gi + 2) = __nv_bfloat162(h2, h3);
            *reinterpret_cast<__nv_bfloat162*>(g_xlo + gi)     = __nv_bfloat162(l0, l1);
            *reinterpret_cast<__nv_bfloat162*>(g_xlo + gi + 2) = __nv_bfloat162(l2, l3);
        }

        // per-head L2 norms -> rk/wk bf16 splits
        {
            float4 xv = reinterpret_cast<float4*>(sx)[w * 32 + lane];
            float4 xs = reinterpret_cast<float4*>(sxp)[w * 32 + lane];
            float s1 = xv.x * xv.x + xv.y * xv.y + xv.z * xv.z + xv.w * xv.w;
            float s2 = xs.x * xs.x + xs.y * xs.y + xs.z * xs.z + xs.w * xs.w;
#pragma unroll
            for (int off = 16; off; off >>= 1) {
                s1 += __shfl_xor_sync(0xffffffffu, s1, off);
                s2 += __shfl_xor_sync(0xffffffffu, s2, off);
            }
            float r1 = rsqrtf(s1 + 1e-6f) * 0.08838834764831845f;
            float r2 = rsqrtf(s2 + 1e-6f);
            long gi = (long)row * D_ + w * K_ + lane * 4;
            __nv_bfloat16 h0, h1, h2, h3, l0, l1, l2, l3;
            bfsplit(xv.x * r1, h0, l0); bfsplit(xv.y * r1, h1, l1);
            bfsplit(xv.z * r1, h2, l2); bfsplit(xv.w * r1, h3, l3);
            *reinterpret_cast<__nv_bfloat162*>(g_rk_h + gi)     = __nv_bfloat162(h0, h1);
            *reinterpret_cast<__nv_bfloat162*>(g_rk_h + gi + 2) = __nv_bfloat162(h2, h3);
            *reinterpret_cast<__nv_bfloat162*>(g_rk_l + gi)     = __nv_bfloat162(l0, l1);
            *reinterpret_cast<__nv_bfloat162*>(g_rk_l + gi + 2) = __nv_bfloat162(l2, l3);
            bfsplit(xs.x * r2, h0, l0); bfsplit(xs.y * r2, h1, l1);
            bfsplit(xs.z * r2, h2, l2); bfsplit(xs.w * r2, h3, l3);
            *reinterpret_cast<__nv_bfloat162*>(g_wk_h + gi)     = __nv_bfloat162(h0, h1);
            *reinterpret_cast<__nv_bfloat162*>(g_wk_h + gi + 2) = __nv_bfloat162(h2, h3);
            *reinterpret_cast<__nv_bfloat162*>(g_wk_l + gi)     = __nv_bfloat162(l0, l1);
            *reinterpret_cast<__nv_bfloat162*>(g_wk_l + gi + 2) = __nv_bfloat162(l2, l3);
        }

        // beta / dec projections
        {
            const float* wb = Wb + w * D_;
            const float* wa = Wa + w * D_;
            float db = 0.f, da = 0.f;
            for (int k = lane; k < D_; k += 32) {
                float xv = sx[k];
                db = fmaf(xv, wb[k], db);
                da = fmaf(xv, wa[k], da);
            }
#pragma unroll
            for (int off = 16; off; off >>= 1) {
                db += __shfl_down_sync(0xffffffffu, db, off);
                da += __shfl_down_sync(0xffffffffu, da, off);
            }
            if (lane == 0) {
                g_beta[row * H_ + w] = 1.f / (1.f + __expf(-db));
                float z = da + dt_bias[w];
                float sp = (z > 20.f) ? z : log1pf(__expf(z));
                g_dec[row * H_ + w] = -__expf(A_log[w]) * sp;
            }
        }
    }
}

// ================= weight splits =================================================
__device__ __forceinline__ void split4(const float* __restrict__ src,
                                       __nv_bfloat16* __restrict__ hi,
                                       __nv_bfloat16* __restrict__ lo, long i) {
    float4 v = *reinterpret_cast<const float4*>(src + i);
    __nv_bfloat16 h0, h1, h2, h3, l0, l1, l2, l3;
    bfsplit(v.x, h0, l0); bfsplit(v.y, h1, l1);
    bfsplit(v.z, h2, l2); bfsplit(v.w, h3, l3);
    *reinterpret_cast<__nv_bfloat162*>(hi + i)     = __nv_bfloat162(h0, h1);
    *reinterpret_cast<__nv_bfloat162*>(hi + i + 2) = __nv_bfloat162(h2, h3);
    *reinterpret_cast<__nv_bfloat162*>(lo + i)     = __nv_bfloat162(l0, l1);
    *reinterpret_cast<__nv_bfloat162*>(lo + i + 2) = __nv_bfloat162(l2, l3);
}
__global__ void __launch_bounds__(256) split_w_k(const float* __restrict__ Wv,
                                                 const float* __restrict__ Wg,
                                                 const float* __restrict__ Wo) {
    long i = ((long)blockIdx.x * 256 + threadIdx.x) * 4;
    if (i < 1048576)            split4(Wv, g_Wvhi, g_Wvlo, i);
    else if (i < 2097152)       split4(Wg, g_Wghi, g_Wglo, i - 1048576);
    else                        split4(Wo, g_Wohi, g_Wolo, i - 2097152);
}

// ================= HMMA split-bf16 GEMM ==========================================
#define TILE_E (128 * GSTR)
#define STAGE_E (4 * TILE_E)
__device__ __forceinline__ void gemm_hmma_body(
    const __nv_bfloat16* __restrict__ Ahi, const __nv_bfloat16* __restrict__ Alo,
    const __nv_bfloat16* __restrict__ Bhi, const __nv_bfloat16* __restrict__ Blo,
    float* __restrict__ Cm) {
    extern __shared__ __nv_bfloat16 dsm[];
    const int tid = threadIdx.x;
    const int wid = tid >> 5, lane = tid & 31;
    const int wm = wid & 1;
    const int wn = wid >> 1;
    const int m0 = blockIdx.y * 128;
    const int n0 = blockIdx.x * 128;

    float acc[4][4][4];
#pragma unroll
    for (int mt = 0; mt < 4; mt++)
#pragma unroll
        for (int nt = 0; nt < 4; nt++)
#pragma unroll
            for (int q = 0; q < 4; q++) acc[mt][nt][q] = 0.f;

    const int lrow = tid >> 2, lseg = (tid & 3) * 8;

    const __nv_bfloat16* gp[4];
    gp[0] = Ahi + (size_t)m0 * 1024;
    gp[1] = Alo + (size_t)m0 * 1024;
    gp[2] = Bhi + (size_t)n0 * 1024;
    gp[3] = Blo + (size_t)n0 * 1024;

    auto load_chunk = [&](int kc, int buf) {
#pragma unroll
        for (int t = 0; t < 4; t++) {
            const __nv_bfloat16* g = gp[t] + kc * 32;
            uint32_t s = smem_u32(&dsm[buf * STAGE_E + t * TILE_E]);
            cpasync16(s + (lrow * GSTR + lseg) * 2, g + (size_t)lrow * 1024 + lseg);
            cpasync16(s + ((lrow + 64) * GSTR + lseg) * 2, g + (size_t)(lrow + 64) * 1024 + lseg);
        }
        CP_COMMIT();
    };

    const int r8 = lane & 7, sel = lane >> 3;

    load_chunk(0, 0);
    for (int kc = 0; kc < 32; kc++) {
        CP_WAIT0();
        __syncthreads();
        if (kc + 1 < 32) load_chunk(kc + 1, (kc + 1) & 1);
        const int buf = kc & 1;
        const uint32_t sAhi = smem_u32(&dsm[buf * STAGE_E + 0 * TILE_E]);
        const uint32_t sAlo = sAhi + TILE_E * 2;
        const uint32_t sBhi = sAhi + 2 * TILE_E * 2;
        const uint32_t sBlo = sAhi + 3 * TILE_E * 2;
#pragma unroll
        for (int ks = 0; ks < 2; ks++) {
            const int k16 = ks * 16;
            const int acol = k16 + (sel >> 1) * 8;
            const int bcol = k16 + (sel & 1) * 8;
            uint32_t ah[4][4], al[4][4], bb[2][4];
#pragma unroll
            for (int mt = 0; mt < 4; mt++) {
                int row = wm * 64 + mt * 16 + (sel & 1) * 8 + r8;
                ldsm4(ah[mt], sAhi + (row * GSTR + acol) * 2);
                ldsm4(al[mt], sAlo + (row * GSTR + acol) * 2);
            }
#pragma unroll
            for (int bt = 0; bt < 2; bt++) {
                int nrow = wn * 32 + bt * 16 + (sel >> 1) * 8 + r8;
                ldsm4(bb[bt], sBhi + (nrow * GSTR + bcol) * 2);
            }
#pragma unroll
            for (int mt = 0; mt < 4; mt++)
#pragma unroll
                for (int nt = 0; nt < 4; nt++) {
                    mma16816(acc[mt][nt], ah[mt], bb[nt >> 1][(nt & 1) * 2], bb[nt >> 1][(nt & 1) * 2 + 1]);
                    mma16816(acc[mt][nt], al[mt], bb[nt >> 1][(nt & 1) * 2], bb[nt >> 1][(nt & 1) * 2 + 1]);
                }
#pragma unroll
            for (int bt = 0; bt < 2; bt++) {
                int nrow = wn * 32 + bt * 16 + (sel >> 1) * 8 + r8;
                ldsm4(bb[bt], sBlo + (nrow * GSTR + bcol) * 2);
            }
#pragma unroll
            for (int mt = 0; mt < 4; mt++)
#pragma unroll
                for (int nt = 0; nt < 4; nt++)
                    mma16816(acc[mt][nt], ah[mt], bb[nt >> 1][(nt & 1) * 2], bb[nt >> 1][(nt & 1) * 2 + 1]);
        }
    }

    const int erow = lane >> 2, ecol = (lane & 3) * 2;
#pragma unroll
    for (int mt = 0; mt < 4; mt++) {
        const size_t row0 = (size_t)(m0 + wm * 64 + mt * 16 + erow);
#pragma unroll
        for (int nt = 0; nt < 4; nt++) {
            const size_t cb = (size_t)(n0 + wn * 32 + nt * 8 + ecol);
            *reinterpret_cast<float2*>(Cm + row0 * 1024 + cb) =
                make_float2(acc[mt][nt][0], acc[mt][nt][1]);
            *reinterpret_cast<float2*>(Cm + (row0 + 8) * 1024 + cb) =
                make_float2(acc[mt][nt][2], acc[mt][nt][3]);
        }
    }
}

__global__ void __launch_bounds__(256, 2) gemm_v_tc() { gemm_hmma_body(g_xhi, g_xlo, g_Wvhi, g_Wvlo, g_xwv); }
__global__ void __launch_bounds__(256, 2) gemm_g_tc() { gemm_hmma_body(g_xhi, g_xlo, g_Wghi, g_Wglo, g_gate); }
__global__ void __launch_bounds__(256, 2) gemm_o_tc(float* __restrict__ out) {
    gemm_hmma_body(g_ahi, g_alo, g_Wohi, g_Wolo, out);
}

// ---------------- causal depthwise conv + SiLU + beta (4 outputs/thread) --------
__global__ void __launch_bounds__(256) conv_silu(const float* __restrict__ conv_w,
                                                 const float* __restrict__ conv_b) {
    const int gb = blockIdx.x;
    const int dblk = gb & 3;
    const long tg = (long)(gb >> 2);
    const int d = dblk * 256 + threadIdx.x;
    const long bt0 = tg * 4;
    const int t0 = (int)(bt0 & (T_ - 1));
    const int h = d >> 7;

    float xr[7];
#pragma unroll
    for (int j = 0; j < 7; j++) {
        int tt = t0 - 3 + j;
        xr[j] = (tt >= 0) ? g_xwv[(bt0 - 3 + j) * D_ + d] : 0.f;
    }
    const float bs = conv_b[d];
    const float w0 = conv_w[d * 4 + 0], w1 = conv_w[d * 4 + 1];
    const float w2 = conv_w[d * 4 + 2], w3 = conv_w[d * 4 + 3];
#pragma unroll
    for (int i = 0; i < 4; i++) {
        float a = bs;
        a = fmaf(xr[i + 0], w0, a);
        a = fmaf(xr[i + 1], w1, a);
        a = fmaf(xr[i + 2], w2, a);
        a = fmaf(xr[i + 3], w3, a);
        float s = a / (1.f + __expf(-a));
        g_v[(bt0 + i) * D_ + d] = s * g_beta[(bt0 + i) * H_ + h];
    }
}

// ---------------- per-chunk: cumsum, HMMA dots, attn(bf16), blocked solve --------
__global__ void __launch_bounds__(256, 2) chunk_prep() {
    extern __shared__ char cpsm[];
    __nv_bfloat16* swh = (__nv_bfloat16*)cpsm;             // 64*CAB
    __nv_bfloat16* swl = swh + 64 * CAB;
    __nv_bfloat16* srh = swl + 64 * CAB;
    __nv_bfloat16* srl = srh + 64 * CAB;                   // end 69632 B
    float* sA = (float*)(cpsm + 69632);                    // 64*64 fp32 -> end 86016 B
    float* s1 = (float*)(cpsm + 34816);                    // aliases srh/srl
    float* s2 = (float*)cpsm;                              // aliases swh/swl
    __shared__ float sdec[C_], sbeta[C_], sraw[C_];
    const int id = blockIdx.x;
    const int chunk = id & 63;
    const int bh = id >> 6;
    const int b = bh >> 3, h = bh & 7;
    const long t0 = (long)b * T_ + chunk * C_;
    const long base = t0 * D_ + h * K_;
    const int tid = threadIdx.x;
    const int wid = tid >> 5, lane = tid & 31;
    const int g8 = lane >> 3, r8 = lane & 7;

    {
        const uint32_t swh_s = smem_u32(swh), swl_s = smem_u32(swl);
        const uint32_t srh_s = smem_u32(srh), srl_s = smem_u32(srl);
#pragma unroll
        for (int q = 0; q < 4; q++) {
            int u = tid + q * 256;
            int row = u >> 4, seg = (u & 15) * 8;
            uint32_t d = (uint32_t)(row * CAB + seg) * 2;
            long g = base + (long)row * D_ + seg;
            cpasync16(swh_s + d, g_wk_h + g);
            cpasync16(swl_s + d, g_wk_l + g);
            cpasync16(srh_s + d, g_rk_h + g);
            cpasync16(srl_s + d, g_rk_l + g);
        }
        CP_COMMIT();
    }
    if (tid < C_) {
        sraw[tid] = g_dec[(t0 + tid) * H_ + h];
        sbeta[tid] = g_beta[(t0 + tid) * H_ + h];
    }
    __syncthreads();
    if (tid < C_) {
        float acc = 0.f;
        for (int j = 0; j <= tid; j++) acc += sraw[j];
        sdec[tid] = acc;
        g_dcum[(t0 + tid) * H_ + h] = acc;
    }
    CP_WAIT0();
    __syncthreads();

    // HMMA: P = [wk; rk] @ wk^T
    {
        const uint32_t swh_s = smem_u32(swh), swl_s = smem_u32(swl);
        const uint32_t srh_s = smem_u32(srh), srl_s = smem_u32(srl);
        const uint32_t ash = (wid < 4) ? swh_s : srh_s;
        const uint32_t asl = (wid < 4) ? swl_s : srl_s;
        const int am0 = (wid & 3) * 16;
        const int aro = (g8 & 1) * 8 + r8, aco = (g8 >> 1) * 8;
        const int bro = (g8 >> 1) * 8 + r8, bco = (g8 & 1) * 8;
        float acc[8][4];
#pragma unroll
        for (int nt = 0; nt < 8; nt++)
#pragma unroll
            for (int q = 0; q < 4; q++) acc[nt][q] = 0.f;
#pragma unroll
        for (int ks = 0; ks < 8; ks++) {
            uint32_t ah[4], al[4], bh4[4][4], bl4[4][4];
            uint32_t aoff = (uint32_t)((am0 + aro) * CAB + ks * 16 + aco) * 2;
            ldsm4(ah, ash + aoff);
            ldsm4(al, asl + aoff);
#pragma unroll
            for (int bt = 0; bt < 4; bt++) {
                uint32_t boff = (uint32_t)((bt * 16 + bro) * CAB + ks * 16 + bco) * 2;
                ldsm4(bh4[bt], swh_s + boff);
                ldsm4(bl4[bt], swl_s + boff);
            }
#pragma unroll
            for (int nt = 0; nt < 8; nt++) {
                uint32_t b0h = bh4[nt >> 1][(nt & 1) * 2], b1h = bh4[nt >> 1][(nt & 1) * 2 + 1];
                uint32_t b0l = bl4[nt >> 1][(nt & 1) * 2], b1l = bl4[nt >> 1][(nt & 1) * 2 + 1];
                mma16816(acc[nt], ah, b0h, b1h);
                mma16816(acc[nt], al, b0h, b1h);
                mma16816(acc[nt], ah, b0l, b1l);
            }
        }
        const int er = lane >> 2, ec = (lane & 3) * 2;
        const int i1 = am0 + er, i2 = i1 + 8;
        if (wid < 4) {
            const float b1v = sbeta[i1], b2v = sbeta[i2];
            const float d1 = sdec[i1], d2 = sdec[i2];
#pragma unroll
            for (int nt = 0; nt < 8; nt++) {
                const int j = nt * 8 + ec;
                float a00 = (j     < i1) ? -acc[nt][0] * b1v * __expf(d1 - sdec[j])     : 0.f;
                float a01 = (j + 1 < i1) ? -acc[nt][1] * b1v * __expf(d1 - sdec[j + 1]) : 0.f;
                float a10 = (j     < i2) ? -acc[nt][2] * b2v * __expf(d2 - sdec[j])     : 0.f;
                float a11 = (j + 1 < i2) ? -acc[nt][3] * b2v * __expf(d2 - sdec[j + 1]) : 0.f;
                sA[i1 * 64 + j] = a00; sA[i1 * 64 + j + 1] = a01;
                sA[i2 * 64 + j] = a10; sA[i2 * 64 + j + 1] = a11;
            }
        } else {
            const float d1 = sdec[i1], d2 = sdec[i2];
            const long ab = (long)id * 4096;
#pragma unroll
            for (int nt = 0; nt < 8; nt++) {
                const int j = nt * 8 + ec;
                float a00 = (j     <= i1) ? acc[nt][0] * __expf(d1 - sdec[j])     : 0.f;
                float a01 = (j + 1 <= i1) ? acc[nt][1] * __expf(d1 - sdec[j + 1]) : 0.f;
                float a10 = (j     <= i2) ? acc[nt][2] * __expf(d2 - sdec[j])     : 0.f;
                float a11 = (j + 1 <= i2) ? acc[nt][3] * __expf(d2 - sdec[j + 1]) : 0.f;
                __nv_bfloat16 h0, l0, h1, l1;
                bfsplit(a00, h0, l0); bfsplit(a01, h1, l1);
                *reinterpret_cast<__nv_bfloat162*>(g_attn_h + ab + i1 * 64 + j) = __nv_bfloat162(h0, h1);
                *reinterpret_cast<__nv_bfloat162*>(g_attn_l + ab + i1 * 64 + j) = __nv_bfloat162(l0, l1);
                bfsplit(a10, h0, l0); bfsplit(a11, h1, l1);
                *reinterpret_cast<__nv_bfloat162*>(g_attn_h + ab + i2 * 64 + j) = __nv_bfloat162(h0, h1);
                *reinterpret_cast<__nv_bfloat162*>(g_attn_l + ab + i2 * 64 + j) = __nv_bfloat162(l0, l1);
            }
        }
    }
    if (tid < C_) sraw[tid] = sbeta[tid] * __expf(sdec[tid]);
    __syncthreads();

    for (int i = tid; i < C_ * K_; i += 256) {
        int c = i >> 7, k = i & 127;
        float wv = __bfloat162float(swh[c * CAB + k]) + __bfloat162float(swl[c * CAB + k]);
        s1[c * RS + k] = wv * sraw[c];
    }
    __syncthreads();
    for (int i = tid; i < C_ * K_; i += 256) {
        int c = i >> 7, k = i & 127;
        s2[c * RS + k] = g_v[base + (long)c * D_ + k];
    }
    __syncthreads();

    {
        float* sx = (tid < 128) ? s1 : s2;
        const int k = tid & 127;
        for (int i = 1; i < 32; i++) {
            float a = 0.f;
            const float* Ai = sA + i * 64;
#pragma unroll 4
            for (int j = 0; j < i; j++)
                a = fmaf(Ai[j], sx[j * RS + k], a);
            sx[i * RS + k] += a;
        }
        float up[32];
#pragma unroll
        for (int i = 0; i < 32; i++) up[i] = 0.f;
        for (int j = 0; j < 32; j++) {
            float xv = sx[j * RS + k];
#pragma unroll
            for (int i = 0; i < 32; i++)
                up[i] = fmaf(sA[(32 + i) * 64 + j], xv, up[i]);
        }
#pragma unroll
        for (int i = 0; i < 32; i++)
            sx[(32 + i) * RS + k] += up[i];
        for (int i = 33; i < 64; i++) {
            float a = 0.f;
            const float* Ai = sA + i * 64;
#pragma unroll 4
            for (int j = 32; j < i; j++)
                a = fmaf(Ai[j], sx[j * RS + k], a);
            sx[i * RS + k] += a;
        }
    }
    __syncthreads();

    for (int i = tid; i < C_ * K_; i += 256) {
        int c = i >> 7, k = i & 127;
        float u = s1[c * RS + k];
        __nv_bfloat16 hh, ll;
        bfsplit(u, hh, ll);
        g_wkc_h[base + (long)c * D_ + k] = hh;
        g_wkc_l[base + (long)c * D_ + k] = ll;
        g_v[base + (long)c * D_ + k] = s2[c * RS + k];
    }
}

// ---------------- HMMA chunk scan (256 thr, S in registers of warps 0-3) ---------
#define SHS 56     // Shi/Slo, svh/svl, s2h/l bf16
#define SAB 136    // sA / swk bf16
#define STB 72     // attn bf16
#define SVF 36     // sv fp32

__global__ void __launch_bounds__(256) scan_kernel() {
    extern __shared__ char smraw[];
    __nv_bfloat16* sShi = (__nv_bfloat16*)smraw;
    __nv_bfloat16* sSlo = sShi + 128 * SHS;
    __nv_bfloat16* sAh  = sSlo + 128 * SHS;
    __nv_bfloat16* sAl  = sAh + 128 * SAB;
    __nv_bfloat16* sWh  = sAl + 128 * SAB;
    __nv_bfloat16* sWl  = sWh + 64 * SAB;
    __nv_bfloat16* sTh  = sWl + 64 * SAB;
    __nv_bfloat16* sTl  = sTh + 64 * STB;
    __nv_bfloat16* svh  = sTl + 64 * STB;
    __nv_bfloat16* svl  = svh + 64 * SHS;
    __nv_bfloat16* s2h  = svl + 64 * SHS;
    __nv_bfloat16* s2l  = s2h + 64 * SHS;
    float* sv = (float*)(s2l + 64 * SHS);

    const int bh = blockIdx.x >> 2;
    const int slice = blockIdx.x & 3;
    const int b = bh >> 3, h = bh & 7;
    const int j0g = slice * SW;
    const int tid = threadIdx.x;
    const int wid = tid >> 5, lane = tid & 31;
    const int g8 = lane >> 3, r8 = lane & 7;
    const int aro = (g8 & 1) * 8 + r8;
    const int aco = (g8 >> 1) * 8;
    const int bro = (g8 & 1) * 8 + r8;
    const int bco = (g8 >> 1) * 8;
    const int tro = (g8 >> 1) * 8 + r8;
    const int tco = (g8 & 1) * 8;
    const int er = lane >> 2, ec = (lane & 3) * 2;

    const uint32_t sShi_s = smem_u32(sShi), sSlo_s = smem_u32(sSlo);
    const uint32_t sAh_s = smem_u32(sAh), sAl_s = smem_u32(sAl);
    const uint32_t sWh_s = smem_u32(sWh), sWl_s = smem_u32(sWl);
    const uint32_t sTh_s = smem_u32(sTh), sTl_s = smem_u32(sTl);
    const uint32_t svh_s = smem_u32(svh), svl_s = smem_u32(svl);
    const uint32_t s2h_s = smem_u32(s2h), s2l_s = smem_u32(s2l);
    const uint32_t sv_s = smem_u32(sv);

    auto issue_Av = [&](int chunk) {
        const long base = ((long)b * T_ + chunk * C_) * D_ + h * K_;
#pragma unroll
        for (int q = 0; q < 8; q++) {
            int u = tid + q * 256;
            int row = u >> 4, seg = (u & 15) * 8;
            uint32_t d = (uint32_t)(row * SAB + seg) * 2;
            if (row < 64) {
                long g = base + (long)row * D_ + seg;
                cpasync16(sAh_s + d, g_wkc_h + g);
                cpasync16(sAl_s + d, g_wkc_l + g);
            } else {
                long g = base + (long)(row - 64) * D_ + seg;
                cpasync16(sAh_s + d, g_rk_h + g);
                cpasync16(sAl_s + d, g_rk_l + g);
            }
        }
#pragma unroll
        for (int q = 0; q < 2; q++) {
            int u = tid + q * 256;
            int row = u >> 3, seg = (u & 7) * 4;
            cpasync16(sv_s + (uint32_t)(row * SVF + seg) * 4,
                      g_v + base + (long)row * D_ + j0g + seg);
        }
        CP_COMMIT();
    };
    auto issue_W = [&](int chunk) {
        const long base = ((long)b * T_ + chunk * C_) * D_ + h * K_;
        const int lt = tid;
#pragma unroll
        for (int q = 0; q < 8; q++) {
            int u = lt + q * 128;
            int row = u >> 4, seg = (u & 15) * 8;
            uint32_t d = (uint32_t)(row * SAB + seg) * 2;
            long g = base + (long)row * D_ + seg;
            cpasync16(sWh_s + d, g_wk_h + g);
            cpasync16(sWl_s + d, g_wk_l + g);
        }
        CP_COMMIT();
    };
    auto issue_T = [&](int chunk) {
        const int lt = tid - 128;
        const long ab = ((long)bh * NCH + chunk) * 4096;
#pragma unroll
        for (int q = 0; q < 4; q++) {
            int u = lt + q * 128;
            int row = u >> 3, seg = (u & 7) * 8;
            uint32_t d = (uint32_t)(row * STB + seg) * 2;
            cpasync16(sTh_s + d, g_attn_h + ab + row * 64 + seg);
            cpasync16(sTl_s + d, g_attn_l + ab + row * 64 + seg);
        }
        CP_COMMIT();
    };

    float Sreg[2][16];
#pragma unroll
    for (int mt = 0; mt < 2; mt++)
#pragma unroll
        for (int q = 0; q < 16; q++) Sreg[mt][q] = 0.f;

    for (int i = tid; i < 128 * SHS; i += 256) {
        sShi[i] = __float2bfloat16(0.f);
        sSlo[i] = __float2bfloat16(0.f);
    }
    issue_Av(0);
    if (wid < 4) issue_W(0); else issue_T(0);

    const int m0 = wid * 16;

    for (int chunk = 0; chunk < NCH; chunk++) {
        const long t0 = (long)b * T_ + chunk * C_;
        const long obase = t0 * D_ + h * K_;
        CP_WAIT0();
        const int myrow = (wid < 4) ? (m0 + er) : (m0 - 64 + er);
        const float dec63 = g_dcum[(t0 + 63) * H_ + h];
        const float decA = g_dcum[(t0 + myrow) * H_ + h];
        const float decB = g_dcum[(t0 + myrow + 8) * H_ + h];
        __syncthreads();

        // ---- HMMA1: P(128x32) = [wkc; rk] @ S ----
        float acc[4][4];
#pragma unroll
        for (int nt = 0; nt < 4; nt++)
#pragma unroll
            for (int q = 0; q < 4; q++) acc[nt][q] = 0.f;
#pragma unroll
        for (int ks = 0; ks < 8; ks++) {
            uint32_t ah[4], al[4], bhf[2][4], blf[2][4];
            uint32_t aoff = (uint32_t)((m0 + aro) * SAB + ks * 16 + aco) * 2;
            ldsm4(ah, sAh_s + aoff);
            ldsm4(al, sAl_s + aoff);
#pragma unroll
            for (int nh = 0; nh < 2; nh++) {
                uint32_t boff = (uint32_t)((ks * 16 + bro) * SHS + nh * 16 + bco) * 2;
                ldsm4t(bhf[nh], sShi_s + boff);
                ldsm4t(blf[nh], sSlo_s + boff);
            }
#pragma unroll
            for (int nt = 0; nt < 4; nt++) {
                uint32_t b0h = bhf[nt >> 1][(nt & 1) * 2], b1h = bhf[nt >> 1][(nt & 1) * 2 + 1];
                uint32_t b0l = blf[nt >> 1][(nt & 1) * 2], b1l = blf[nt >> 1][(nt & 1) * 2 + 1];
                mma16816(acc[nt], ah, b0h, b1h);
                mma16816(acc[nt], al, b0h, b1h);
                mma16816(acc[nt], ah, b0l, b1l);
            }
        }

        // ---- epilogue 1 ----
        if (wid < 4) {
            const int c1 = m0 + er, c2 = c1 + 8;
            const float dw1 = __expf(dec63 - decA), dw2 = __expf(dec63 - decB);
#pragma unroll
            for (int nt = 0; nt < 4; nt++) {
                const int col = nt * 8 + ec;
                float a0 = sv[c1 * SVF + col]     - acc[nt][0];
                float a1 = sv[c1 * SVF + col + 1] - acc[nt][1];
                float a2 = sv[c2 * SVF + col]     - acc[nt][2];
                float a3 = sv[c2 * SVF + col + 1] - acc[nt][3];
                __nv_bfloat16 h0, l0, h1, l1, h2, l2, h3, l3;
                bfsplit(a0, h0, l0); bfsplit(a1, h1, l1);
                bfsplit(a2, h2, l2); bfsplit(a3, h3, l3);
                *reinterpret_cast<__nv_bfloat162*>(svh + c1 * SHS + col) = __nv_bfloat162(h0, h1);
                *reinterpret_cast<__nv_bfloat162*>(svl + c1 * SHS + col) = __nv_bfloat162(l0, l1);
                *reinterpret_cast<__nv_bfloat162*>(svh + c2 * SHS + col) = __nv_bfloat162(h2, h3);
                *reinterpret_cast<__nv_bfloat162*>(svl + c2 * SHS + col) = __nv_bfloat162(l2, l3);
                float b0 = dw1 * a0, b1 = dw1 * a1, b2 = dw2 * a2, b3 = dw2 * a3;
                bfsplit(b0, h0, l0); bfsplit(b1, h1, l1);
                bfsplit(b2, h2, l2); bfsplit(b3, h3, l3);
                *reinterpret_cast<__nv_bfloat162*>(s2h + c1 * SHS + col) = __nv_bfloat162(h0, h1);
                *reinterpret_cast<__nv_bfloat162*>(s2l + c1 * SHS + col) = __nv_bfloat162(l0, l1);
                *reinterpret_cast<__nv_bfloat162*>(s2h + c2 * SHS + col) = __nv_bfloat162(h2, h3);
                *reinterpret_cast<__nv_bfloat162*>(s2l + c2 * SHS + col) = __nv_bfloat162(l2, l3);
            }
        } else {
            const float e1 = __expf(decA), e2 = __expf(decB);
#pragma unroll
            for (int nt = 0; nt < 4; nt++) {
                acc[nt][0] *= e1; acc[nt][1] *= e1;
                acc[nt][2] *= e2; acc[nt][3] *= e2;
            }
        }
        __syncthreads();
        if (chunk + 1 < NCH) issue_Av(chunk + 1);

        if (wid >= 4) {
            const int m0o = (wid - 4) * 16;
#pragma unroll
            for (int ks = 0; ks < 4; ks++) {
                uint32_t ah[4], al[4], bhf[2][4], blf[2][4];
                uint32_t aoff = (uint32_t)((m0o + aro) * STB + ks * 16 + aco) * 2;
                ldsm4(ah, sTh_s + aoff);
                ldsm4(al, sTl_s + aoff);
#pragma unroll
                for (int nh = 0; nh < 2; nh++) {
                    uint32_t boff = (uint32_t)((ks * 16 + bro) * SHS + nh * 16 + bco) * 2;
                    ldsm4t(bhf[nh], svh_s + boff);
                    ldsm4t(blf[nh], svl_s + boff);
                }
#pragma unroll
                for (int nt = 0; nt < 4; nt++) {
                    uint32_t b0h = bhf[nt >> 1][(nt & 1) * 2], b1h = bhf[nt >> 1][(nt & 1) * 2 + 1];
                    uint32_t b0l = blf[nt >> 1][(nt & 1) * 2], b1l = blf[nt >> 1][(nt & 1) * 2 + 1];
                    mma16816(acc[nt], ah, b0h, b1h);
                    mma16816(acc[nt], al, b0h, b1h);
                    mma16816(acc[nt], ah, b0l, b1l);
                }
            }
            const int c1 = m0o + er, c2 = c1 + 8;
#pragma unroll
            for (int nt = 0; nt < 4; nt++) {
                const int col = nt * 8 + ec;
                *reinterpret_cast<float2*>(g_o + obase + (long)c1 * D_ + j0g + col) =
                    make_float2(acc[nt][0], acc[nt][1]);
                *reinterpret_cast<float2*>(g_o + obase + (long)c2 * D_ + j0g + col) =
                    make_float2(acc[nt][2], acc[nt][3]);
            }
            if (chunk + 1 < NCH) issue_T(chunk + 1);
        } else {
            const float e63 = __expf(dec63);
#pragma unroll
            for (int mt = 0; mt < 2; mt++) {
                const int m0s = wid * 32 + mt * 16;
                float a2c[4][4];
#pragma unroll
                for (int nt = 0; nt < 4; nt++)
#pragma unroll
                    for (int q = 0; q < 4; q++) a2c[nt][q] = 0.f;
#pragma unroll
                for (int ks = 0; ks < 4; ks++) {
                    uint32_t ah[4], al[4], bhf[2][4], blf[2][4];
                    uint32_t aoff = (uint32_t)((ks * 16 + tro) * SAB + m0s + tco) * 2;
                    ldsm4t(ah, sWh_s + aoff);
                    ldsm4t(al, sWl_s + aoff);
#pragma unroll
                    for (int nh = 0; nh < 2; nh++) {
                        uint32_t boff = (uint32_t)((ks * 16 + bro) * SHS + nh * 16 + bco) * 2;
                        ldsm4t(bhf[nh], s2h_s + boff);
                        ldsm4t(blf[nh], s2l_s + boff);
                    }
#pragma unroll
                    for (int nt = 0; nt < 4; nt++) {
                        uint32_t b0h = bhf[nt >> 1][(nt & 1) * 2], b1h = bhf[nt >> 1][(nt & 1) * 2 + 1];
                        uint32_t b0l = blf[nt >> 1][(nt & 1) * 2], b1l = blf[nt >> 1][(nt & 1) * 2 + 1];
                        mma16816(a2c[nt], ah, b0h, b1h);
                        mma16816(a2c[nt], al, b0h, b1h);
                        mma16816(a2c[nt], ah, b0l, b1l);
                    }
                }
                const int k1 = m0s + er, k2 = k1 + 8;
#pragma unroll
                for (int nt = 0; nt < 4; nt++) {
                    const int col = nt * 8 + ec;
                    float n00 = Sreg[mt][nt * 4 + 0] * e63 + a2c[nt][0];
                    float n01 = Sreg[mt][nt * 4 + 1] * e63 + a2c[nt][1];
                    float n10 = Sreg[mt][nt * 4 + 2] * e63 + a2c[nt][2];
                    float n11 = Sreg[mt][nt * 4 + 3] * e63 + a2c[nt][3];
                    Sreg[mt][nt * 4 + 0] = n00; Sreg[mt][nt * 4 + 1] = n01;
                    Sreg[mt][nt * 4 + 2] = n10; Sreg[mt][nt * 4 + 3] = n11;
                    __nv_bfloat16 hh, ll;
                    bfsplit(n00, hh, ll); sShi[k1 * SHS + col] = hh;     sSlo[k1 * SHS + col] = ll;
                    bfsplit(n01, hh, ll); sShi[k1 * SHS + col + 1] = hh; sSlo[k1 * SHS + col + 1] = ll;
                    bfsplit(n10, hh, ll); sShi[k2 * SHS + col] = hh;     sSlo[k2 * SHS + col] = ll;
                    bfsplit(n11, hh, ll); sShi[k2 * SHS + col + 1] = hh; sSlo[k2 * SHS + col + 1] = ll;
                }
            }
            if (chunk + 1 < NCH) issue_W(chunk + 1);
        }
    }
}

// ---------------- per-head RMSNorm + gated SiLU (warp per row) -------------------
__global__ void __launch_bounds__(256) rms_gate(const float* __restrict__ norm_w) {
    const int row = blockIdx.x * 8 + (threadIdx.x >> 5);
    const int lane = threadIdx.x & 31;
    const long gi = (long)row * K_ + lane * 4;
    float4 ov = *reinterpret_cast<const float4*>(g_o + gi);
    float s = ov.x * ov.x + ov.y * ov.y + ov.z * ov.z + ov.w * ov.w;
#pragma unroll
    for (int off = 16; off; off >>= 1) s += __shfl_xor_sync(0xffffffffu, s, off);
    float r = rsqrtf(s * (1.f / 128.f) + 1e-5f);
    float4 g = *reinterpret_cast<const float4*>(g_gate + gi);
    float4 nw = *reinterpret_cast<const float4*>(norm_w + lane * 4);
    float v0 = ov.x * r * nw.x * (g.x / (1.f + __expf(-g.x)));
    float v1 = ov.y * r * nw.y * (g.y / (1.f + __expf(-g.y)));
    float v2 = ov.z * r * nw.z * (g.z / (1.f + __expf(-g.z)));
    float v3 = ov.w * r * nw.w * (g.w / (1.f + __expf(-g.w)));
    __nv_bfloat16 h0, l0, h1, l1, h2, l2, h3, l3;
    bfsplit(v0, h0, l0); bfsplit(v1, h1, l1);
    bfsplit(v2, h2, l2); bfsplit(v3, h3, l3);
    *reinterpret_cast<__nv_bfloat162*>(g_ahi + gi)     = __nv_bfloat162(h0, h1);
    *reinterpret_cast<__nv_bfloat162*>(g_ahi + gi + 2) = __nv_bfloat162(h2, h3);
    *reinterpret_cast<__nv_bfloat162*>(g_alo + gi)     = __nv_bfloat162(l0, l1);
    *reinterpret_cast<__nv_bfloat162*>(g_alo + gi + 2) = __nv_bfloat162(l2, l3);
}

// ---------------- launcher ------------------------------------------------------
extern "C" void kernel_launch(void* const* d_in, const int* in_sizes, int n_in,
                              void* d_out, int out_size) {
    const float* x       = (const float*)d_in[0];
    const float* Wv      = (const float*)d_in[1];
    const float* Wg      = (const float*)d_in[2];
    const float* Wo      = (const float*)d_in[3];
    const float* Wb      = (const float*)d_in[4];
    const float* Wa      = (const float*)d_in[5];
    const float* dt_bias = (const float*)d_in[6];
    const float* A_log   = (const float*)d_in[7];
    const float* norm_w  = (const float*)d_in[8];
    const float* conv_w  = (const float*)d_in[9];
    const float* conv_b  = (const float*)d_in[10];
    float* out = (float*)d_out;

    const int CP_SMEM   = 86016;
    const int SCAN_SMEM = (2 * 128 * SHS + 2 * 128 * SAB + 2 * 64 * SAB +
                           2 * 64 * STB + 4 * 64 * SHS) * 2 + 64 * SVF * 4;
    const int GEMM_SMEM = 2 * STAGE_E * 2;
    cudaFuncSetAttribute(chunk_prep,  cudaFuncAttributeMaxDynamicSharedMemorySize, CP_SMEM);
    cudaFuncSetAttribute(scan_kernel, cudaFuncAttributeMaxDynamicSharedMemorySize, SCAN_SMEM);
    cudaFuncSetAttribute(gemm_v_tc,   cudaFuncAttributeMaxDynamicSharedMemorySize, GEMM_SMEM);
    cudaFuncSetAttribute(gemm_g_tc,   cudaFuncAttributeMaxDynamicSharedMemorySize, GEMM_SMEM);
    cudaFuncSetAttribute(gemm_o_tc,   cudaFuncAttributeMaxDynamicSharedMemorySize, GEMM_SMEM);

    dim3 gg(D_ / 128, M_ / 128);

    if (s_ok) {
        cudaEventRecord(ev_root, 0);
        cudaStreamWaitEvent(s_aux2, ev_root, 0);
        split_w_k<<<(3 * D_ * D_) / 1024, 256, 0, s_aux2>>>(Wv, Wg, Wo);
        cudaEventRecord(ev_w, s_aux2);
        prep_tokens<<<M_ / 4, 256>>>(x, Wb, Wa, dt_bias, A_log);
        cudaEventRecord(ev_p, 0);
        cudaStreamWaitEvent(s_aux1, ev_w, 0);
        cudaStreamWaitEvent(s_aux1, ev_p, 0);
        gemm_g_tc<<<gg, 256, GEMM_SMEM, s_aux1>>>();
        cudaEventRecord(ev_g, s_aux1);
        cudaStreamWaitEvent(0, ev_w, 0);
        gemm_v_tc<<<gg, 256, GEMM_SMEM>>>();
        conv_silu<<<(B_ * T_ / 4) * (D_ / 256), 256>>>(conv_w, conv_b);
        chunk_prep<<<B_ * H_ * NCH, 256, CP_SMEM>>>();
        scan_kernel<<<B_ * H_ * SLICES, 256, SCAN_SMEM>>>();
        cudaStreamWaitEvent(0, ev_g, 0);
        rms_gate<<<M_ * H_ / 8, 256>>>(norm_w);
        gemm_o_tc<<<gg, 256, GEMM_SMEM>>>(out);
    } else {
        prep_tokens<<<M_ / 4, 256>>>(x, Wb, Wa, dt_bias, A_log);
        split_w_k<<<(3 * D_ * D_) / 1024, 256>>>(Wv, Wg, Wo);
        gemm_v_tc<<<gg, 256, GEMM_SMEM>>>();
        gemm_g_tc<<<gg, 256, GEMM_SMEM>>>();
        conv_silu<<<(B_ * T_ / 4) * (D_ / 256), 256>>>(conv_w, conv_b);
        chunk_prep<<<B_ * H_ * NCH, 256, CP_SMEM>>>();
        scan_kernel<<<B_ * H_ * SLICES, 256, SCAN_SMEM>>>();
        rms_gate<<<M_ * H_ / 8, 256>>>(norm_w);
        gemm_o_tc<<<gg, 256, GEMM_SMEM>>>(out);
    }
}